// round 1
// baseline (speedup 1.0000x reference)
#include <cuda_runtime.h>

// Problem constants
#define BB   4      // batch
#define CIN  3
#define C1   32     // conv1 out channels (16x16 spatial)
#define C2   64     // conv2 out channels (8x8 spatial)
#define MM   512    // hopfield memory slots
#define DD   64     // token dim (== C2)

// Scratch (allocation-free rule: __device__ globals)
__device__ float g_a1[BB*C1*16*16];   // relu(conv1(x)+b1)
__device__ float g_v1[BB*C1*16*16];   // mask1 * (conv1(x))   (JVP, no bias)
__device__ float g_zq[BB*C2*64];      // masked JVP output (B, C2, 64 spatial)
__device__ float g_V [MM*DD];         // lookup @ Wv

// ---------------------------------------------------------------------------
// Kernel 1: conv1 (stride 2, pad 1, k=4) forward + JVP value.
// One thread per output element: (b, oc, oy, ox) over 4*32*16*16 = 32768.
// ---------------------------------------------------------------------------
__global__ void conv1_kernel(const float* __restrict__ x,
                             const float* __restrict__ w,
                             const float* __restrict__ bias) {
    int idx = blockIdx.x * blockDim.x + threadIdx.x;
    if (idx >= BB*C1*16*16) return;
    int ox = idx & 15;
    int oy = (idx >> 4) & 15;
    int oc = (idx >> 8) & 31;
    int b  = idx >> 13;

    float s = 0.f;
    #pragma unroll
    for (int ic = 0; ic < CIN; ic++) {
        const float* xp = x + (b*CIN + ic) * 1024;        // 32*32
        const float* wp = w + (oc*CIN + ic) * 16;         // 4*4
        #pragma unroll
        for (int ky = 0; ky < 4; ky++) {
            int iy = oy*2 - 1 + ky;
            if (iy < 0 || iy >= 32) continue;
            #pragma unroll
            for (int kx = 0; kx < 4; kx++) {
                int ix = ox*2 - 1 + kx;
                if (ix < 0 || ix >= 32) continue;
                s += xp[iy*32 + ix] * wp[ky*4 + kx];
            }
        }
    }
    float pre = s + bias[oc];
    bool on = pre > 0.f;
    g_a1[idx] = on ? pre : 0.f;
    g_v1[idx] = on ? s   : 0.f;
}

// ---------------------------------------------------------------------------
// Kernel 2: conv2 (stride 2, pad 1, k=4) forward-mask + JVP.
// One thread per output element: (b, oc, oy, ox) over 4*64*8*8 = 16384.
// z_q[b][oc][n] = (pre2>0) ? (W2 * v1) : 0,  pre2 = W2 * a1 + b2
// ---------------------------------------------------------------------------
__global__ void conv2_kernel(const float* __restrict__ w,
                             const float* __restrict__ bias) {
    int idx = blockIdx.x * blockDim.x + threadIdx.x;
    if (idx >= BB*C2*64) return;
    int ox = idx & 7;
    int oy = (idx >> 3) & 7;
    int oc = (idx >> 6) & 63;
    int b  = idx >> 12;

    float sA = 0.f, sV = 0.f;
    for (int ic = 0; ic < C1; ic++) {
        const float* ap = g_a1 + (b*C1 + ic) * 256;       // 16*16
        const float* vp = g_v1 + (b*C1 + ic) * 256;
        const float* wp = w + (oc*C1 + ic) * 16;
        #pragma unroll
        for (int ky = 0; ky < 4; ky++) {
            int iy = oy*2 - 1 + ky;
            if (iy < 0 || iy >= 16) continue;
            #pragma unroll
            for (int kx = 0; kx < 4; kx++) {
                int ix = ox*2 - 1 + kx;
                if (ix < 0 || ix >= 16) continue;
                float wv = wp[ky*4 + kx];
                sA += ap[iy*16 + ix] * wv;
                sV += vp[iy*16 + ix] * wv;
            }
        }
    }
    float pre = sA + bias[oc];
    g_zq[(b*C2 + oc) * 64 + (oy*8 + ox)] = (pre > 0.f) ? sV : 0.f;
}

// ---------------------------------------------------------------------------
// Kernel 3: V = lookup @ Wv.  Grid 512 blocks x 64 threads.
// ---------------------------------------------------------------------------
__global__ void vproj_kernel(const float* __restrict__ lookup,
                             const float* __restrict__ Wv) {
    int m = blockIdx.x;
    int d = threadIdx.x;
    __shared__ float row[DD];
    row[d] = lookup[m*DD + d];
    __syncthreads();
    float s = 0.f;
    #pragma unroll
    for (int k = 0; k < DD; k++)
        s += row[k] * Wv[k*DD + d];    // coalesced over d
    g_V[m*DD + d] = s;
}

// ---------------------------------------------------------------------------
// Kernel 4: Hopfield retrieval per (b, n) token row, 256 threads per block.
//   scores[m] = (z_q[b,:,n] . lookup[m,:]) / 8
//   p = softmax(scores);  tmp = p @ V;  out = tmp @ Wo
//   d_out[(b*64 + e)*64 + n] = out[e]   (the (0,2,1) transpose)
// ---------------------------------------------------------------------------
__global__ void hopfield_kernel(const float* __restrict__ lookup,
                                const float* __restrict__ Wo,
                                float* __restrict__ out) {
    int n = blockIdx.x;   // spatial position 0..63
    int b = blockIdx.y;   // batch 0..3
    int tid = threadIdx.x;

    __shared__ float t[DD];
    __shared__ float sc[MM];
    __shared__ float red[256];
    __shared__ float part[256];
    __shared__ float tmp[DD];

    if (tid < DD) t[tid] = g_zq[(b*C2 + tid) * 64 + n];
    __syncthreads();

    // scores
    for (int m = tid; m < MM; m += 256) {
        const float* lp = lookup + m*DD;
        float s = 0.f;
        #pragma unroll
        for (int d = 0; d < DD; d++) s += t[d] * lp[d];
        sc[m] = s * 0.125f;   // 1/sqrt(64)
    }
    __syncthreads();

    // max reduce
    float lm = -1e30f;
    for (int m = tid; m < MM; m += 256) lm = fmaxf(lm, sc[m]);
    red[tid] = lm;
    __syncthreads();
    for (int s = 128; s > 0; s >>= 1) {
        if (tid < s) red[tid] = fmaxf(red[tid], red[tid + s]);
        __syncthreads();
    }
    float mx = red[0];
    __syncthreads();

    // exp + sum reduce
    float ls = 0.f;
    for (int m = tid; m < MM; m += 256) {
        float e = __expf(sc[m] - mx);
        sc[m] = e;
        ls += e;
    }
    red[tid] = ls;
    __syncthreads();
    for (int s = 128; s > 0; s >>= 1) {
        if (tid < s) red[tid] += red[tid + s];
        __syncthreads();
    }
    float total = red[0];
    __syncthreads();

    // retrieval: tmp[d] = (1/total) * sum_m sc[m] * V[m][d]
    // thread layout: d = tid & 63, chunk c = tid >> 6 (4 chunks of 128 m each)
    {
        int d = tid & 63;
        int c = tid >> 6;
        float acc = 0.f;
        int m0 = c * 128, m1 = m0 + 128;
        for (int m = m0; m < m1; m++)
            acc += sc[m] * g_V[m*DD + d];
        part[tid] = acc;
    }
    __syncthreads();
    if (tid < DD) {
        tmp[tid] = (part[tid] + part[tid + 64] + part[tid + 128] + part[tid + 192])
                   / total;
    }
    __syncthreads();

    // output projection + transposed store
    if (tid < DD) {
        int e = tid;
        float o = 0.f;
        #pragma unroll
        for (int d = 0; d < DD; d++) o += tmp[d] * Wo[d*DD + e];
        out[(b*C2 + e) * 64 + n] = o;
    }
}

// ---------------------------------------------------------------------------
extern "C" void kernel_launch(void* const* d_in, const int* in_sizes, int n_in,
                              void* d_out, int out_size) {
    const float* x       = (const float*)d_in[0];
    const float* conv1_w = (const float*)d_in[1];
    const float* conv1_b = (const float*)d_in[2];
    const float* conv2_w = (const float*)d_in[3];
    const float* conv2_b = (const float*)d_in[4];
    const float* lookup  = (const float*)d_in[5];
    const float* Wv      = (const float*)d_in[6];
    const float* Wo      = (const float*)d_in[7];
    float* out = (float*)d_out;

    conv1_kernel<<<(BB*C1*16*16 + 255)/256, 256>>>(x, conv1_w, conv1_b);
    vproj_kernel<<<MM, DD>>>(lookup, Wv);              // independent of conv path
    conv2_kernel<<<(BB*C2*64 + 255)/256, 256>>>(conv2_w, conv2_b);
    hopfield_kernel<<<dim3(64, BB), 256>>>(lookup, Wo, out);
}

// round 2
// speedup vs baseline: 2.7027x; 2.7027x over previous
#include <cuda_runtime.h>

// Problem constants
#define BB   4      // batch
#define CIN  3
#define C1   32     // conv1 out channels (16x16 spatial)
#define C2   64     // conv2 out channels (8x8 spatial)
#define MM   512    // hopfield memory slots
#define DD   64     // token dim (== C2)
#define NTOK 4      // tokens per hopfield block

// Scratch (allocation-free rule: __device__ globals)
__device__ float g_a1[BB*C1*16*16];   // relu(conv1(x)+b1)
__device__ float g_v1[BB*C1*16*16];   // mask1 * conv1(x)   (JVP, no bias)
__device__ float g_zq[BB*C2*64];      // masked JVP output (B, C2, 64 spatial)
__device__ float g_V [MM*DD];         // lookup @ Wv

// ---------------------------------------------------------------------------
// Kernel 1: conv1 (stride 2, pad 1, k=4) forward + JVP value.
// One thread per output element: (b, oc, oy, ox) over 4*32*16*16 = 32768.
// ---------------------------------------------------------------------------
__global__ void conv1_kernel(const float* __restrict__ x,
                             const float* __restrict__ w,
                             const float* __restrict__ bias) {
    int idx = blockIdx.x * blockDim.x + threadIdx.x;
    if (idx >= BB*C1*16*16) return;
    int ox = idx & 15;
    int oy = (idx >> 4) & 15;
    int oc = (idx >> 8) & 31;
    int b  = idx >> 13;

    float s = 0.f;
    #pragma unroll
    for (int ic = 0; ic < CIN; ic++) {
        const float* xp = x + (b*CIN + ic) * 1024;
        const float* wp = w + (oc*CIN + ic) * 16;
        #pragma unroll
        for (int ky = 0; ky < 4; ky++) {
            int iy = oy*2 - 1 + ky;
            if (iy < 0 || iy >= 32) continue;
            #pragma unroll
            for (int kx = 0; kx < 4; kx++) {
                int ix = ox*2 - 1 + kx;
                if (ix < 0 || ix >= 32) continue;
                s += __ldg(&xp[iy*32 + ix]) * __ldg(&wp[ky*4 + kx]);
            }
        }
    }
    float pre = s + bias[oc];
    bool on = pre > 0.f;
    g_a1[idx] = on ? pre : 0.f;
    g_v1[idx] = on ? s   : 0.f;
}

// ---------------------------------------------------------------------------
// Kernel 2: conv2 forward-mask + JVP, ic split across even/odd lanes.
// 32768 threads (pairs), shuffle-combine. 128 blocks.
// ---------------------------------------------------------------------------
__global__ void conv2_kernel(const float* __restrict__ w,
                             const float* __restrict__ bias) {
    int gid = blockIdx.x * blockDim.x + threadIdx.x;
    if (gid >= 2*BB*C2*64) return;
    int h = gid & 1;          // ic-half
    int p = gid >> 1;         // output index
    int ox = p & 7;
    int oy = (p >> 3) & 7;
    int oc = (p >> 6) & 63;
    int b  = p >> 12;

    float sA = 0.f, sV = 0.f;
    int ic0 = h * 16;
    for (int ic = ic0; ic < ic0 + 16; ic++) {
        const float* ap = g_a1 + (b*C1 + ic) * 256;
        const float* vp = g_v1 + (b*C1 + ic) * 256;
        const float* wp = w + (oc*C1 + ic) * 16;
        #pragma unroll
        for (int ky = 0; ky < 4; ky++) {
            int iy = oy*2 - 1 + ky;
            if (iy < 0 || iy >= 16) continue;
            #pragma unroll
            for (int kx = 0; kx < 4; kx++) {
                int ix = ox*2 - 1 + kx;
                if (ix < 0 || ix >= 16) continue;
                float wv = __ldg(&wp[ky*4 + kx]);
                sA += __ldg(&ap[iy*16 + ix]) * wv;
                sV += __ldg(&vp[iy*16 + ix]) * wv;
            }
        }
    }
    sA += __shfl_xor_sync(0xFFFFFFFFu, sA, 1);
    sV += __shfl_xor_sync(0xFFFFFFFFu, sV, 1);
    if (h == 0) {
        float pre = sA + bias[oc];
        g_zq[(b*C2 + oc) * 64 + (oy*8 + ox)] = (pre > 0.f) ? sV : 0.f;
    }
}

// ---------------------------------------------------------------------------
// Kernel 3: V = lookup @ Wv.  Grid 512 blocks x 64 threads.
// ---------------------------------------------------------------------------
__global__ void vproj_kernel(const float* __restrict__ lookup,
                             const float* __restrict__ Wv) {
    int m = blockIdx.x;
    int d = threadIdx.x;
    __shared__ float row[DD];
    row[d] = lookup[m*DD + d];
    __syncthreads();
    float s = 0.f;
    #pragma unroll
    for (int k = 0; k < DD; k++)
        s += row[k] * Wv[k*DD + d];    // coalesced over d
    g_V[m*DD + d] = s;
}

// ---------------------------------------------------------------------------
// Kernel 4: Hopfield retrieval, 4 tokens per block, 256 threads.
// Grid: (16 n-groups, B). lookup staged fully in smem (pad 65, conflict-free).
// ---------------------------------------------------------------------------
__global__ void hopfield_kernel(const float* __restrict__ lookup,
                                const float* __restrict__ Wo,
                                float* __restrict__ out) {
    extern __shared__ float smem[];
    // layout (floats):
    float4* pS4   = (float4*)smem;             // 512 float4: probs [m][4]
    float4* red4  = pS4 + MM;                  // 256 float4: reduction
    float*  Lsm   = (float*)(red4 + 256);      // 512*65
    float*  tS    = Lsm + MM*65;               // 64*4  tokens [d][j]
    float*  tmpS  = tS + DD*NTOK;              // 4*64  retrieved [j][d]
    float*  partS = tmpS + NTOK*DD;            // 256*4 partials [c][d][j]
    float*  oS    = partS + 1024;              // 64*4  out [e][j]

    int ng  = blockIdx.x;          // token group (4 n)
    int b   = blockIdx.y;
    int n0  = ng * NTOK;
    int tid = threadIdx.x;

    // stage lookup: coalesced gmem reads, padded smem rows
    for (int i = tid; i < MM*DD; i += 256) {
        int m = i >> 6, d = i & 63;
        Lsm[m*65 + d] = lookup[i];
    }
    // stage tokens transposed: tS[d][j]
    {
        int j = tid & 3, d = tid >> 2;
        tS[d*NTOK + j] = g_zq[(b*C2 + d) * 64 + n0 + j];
    }
    __syncthreads();

    // --- scores: thread owns m = tid and m+256, all 4 tokens ---
    float aL0=0.f, aL1=0.f, aL2=0.f, aL3=0.f;
    float aH0=0.f, aH1=0.f, aH2=0.f, aH3=0.f;
    {
        const float* l0 = &Lsm[tid*65];
        const float* l1 = &Lsm[(tid+256)*65];
        #pragma unroll 8
        for (int d = 0; d < DD; d++) {
            float4 tv = *(const float4*)&tS[d*NTOK];
            float a = l0[d], c = l1[d];
            aL0 += a*tv.x; aL1 += a*tv.y; aL2 += a*tv.z; aL3 += a*tv.w;
            aH0 += c*tv.x; aH1 += c*tv.y; aH2 += c*tv.z; aH3 += c*tv.w;
        }
    }
    const float scale = 0.125f;  // 1/sqrt(64)
    aL0*=scale; aL1*=scale; aL2*=scale; aL3*=scale;
    aH0*=scale; aH1*=scale; aH2*=scale; aH3*=scale;

    // --- block max (float4-wide) ---
    float4 m4 = make_float4(fmaxf(aL0,aH0), fmaxf(aL1,aH1),
                            fmaxf(aL2,aH2), fmaxf(aL3,aH3));
    red4[tid] = m4;
    __syncthreads();
    for (int s = 128; s > 0; s >>= 1) {
        if (tid < s) {
            float4 x = red4[tid], y = red4[tid+s];
            red4[tid] = make_float4(fmaxf(x.x,y.x), fmaxf(x.y,y.y),
                                    fmaxf(x.z,y.z), fmaxf(x.w,y.w));
        }
        __syncthreads();
    }
    float4 MX = red4[0];
    __syncthreads();

    // --- exp + block sum ---
    float4 eL = make_float4(__expf(aL0-MX.x), __expf(aL1-MX.y),
                            __expf(aL2-MX.z), __expf(aL3-MX.w));
    float4 eH = make_float4(__expf(aH0-MX.x), __expf(aH1-MX.y),
                            __expf(aH2-MX.z), __expf(aH3-MX.w));
    pS4[tid]     = eL;
    pS4[tid+256] = eH;
    red4[tid] = make_float4(eL.x+eH.x, eL.y+eH.y, eL.z+eH.z, eL.w+eH.w);
    __syncthreads();
    for (int s = 128; s > 0; s >>= 1) {
        if (tid < s) {
            float4 x = red4[tid], y = red4[tid+s];
            red4[tid] = make_float4(x.x+y.x, x.y+y.y, x.z+y.z, x.w+y.w);
        }
        __syncthreads();
    }
    float4 SUM = red4[0];
    __syncthreads();

    // --- retrieval: tmp[j][d] = sum_m p[j][m] * V[m][d] ---
    {
        int d = tid & 63, c = tid >> 6;   // 4 m-chunks of 128
        float r0=0.f, r1=0.f, r2=0.f, r3=0.f;
        int m0 = c * 128;
        const float* vp = g_V + (size_t)m0*DD + d;
        #pragma unroll 4
        for (int m = 0; m < 128; m++) {
            float4 p = pS4[m0 + m];          // broadcast across lanes
            float v = __ldg(vp); vp += DD;   // coalesced over d
            r0 += p.x*v; r1 += p.y*v; r2 += p.z*v; r3 += p.w*v;
        }
        ((float4*)partS)[c*64 + d] = make_float4(r0, r1, r2, r3);
    }
    __syncthreads();
    {
        int j = tid >> 6, d = tid & 63;
        float inv = 1.f / ((j==0)?SUM.x:(j==1)?SUM.y:(j==2)?SUM.z:SUM.w);
        float t = partS[(0*64+d)*4 + j] + partS[(1*64+d)*4 + j]
                + partS[(2*64+d)*4 + j] + partS[(3*64+d)*4 + j];
        tmpS[j*DD + d] = t * inv;
    }
    __syncthreads();

    // --- output projection: out[j][e] = sum_d tmp[j][d] * Wo[d][e] ---
    {
        int j = tid >> 6, e = tid & 63;
        float o = 0.f;
        const float* tp = &tmpS[j*DD];
        #pragma unroll 8
        for (int d = 0; d < DD; d++)
            o += tp[d] * __ldg(&Wo[d*DD + e]);   // coalesced over e
        oS[e*NTOK + j] = o;
    }
    __syncthreads();
    if (tid < DD) {
        float4 ov = ((float4*)oS)[tid];
        *(float4*)&out[(b*C2 + tid) * 64 + n0] = ov;
    }
}

// ---------------------------------------------------------------------------
extern "C" void kernel_launch(void* const* d_in, const int* in_sizes, int n_in,
                              void* d_out, int out_size) {
    const float* x       = (const float*)d_in[0];
    const float* conv1_w = (const float*)d_in[1];
    const float* conv1_b = (const float*)d_in[2];
    const float* conv2_w = (const float*)d_in[3];
    const float* conv2_b = (const float*)d_in[4];
    const float* lookup  = (const float*)d_in[5];
    const float* Wv      = (const float*)d_in[6];
    const float* Wo      = (const float*)d_in[7];
    float* out = (float*)d_out;

    // dynamic smem size for hopfield (floats)
    const int smem_floats = MM*4 /*pS4*/ + 256*4 /*red4*/ + MM*65 /*Lsm*/
                          + DD*NTOK + NTOK*DD + 1024 + DD*NTOK;
    const size_t smem_bytes = smem_floats * sizeof(float);
    static bool attr_set = false;
    if (!attr_set) {
        cudaFuncSetAttribute(hopfield_kernel,
                             cudaFuncAttributeMaxDynamicSharedMemorySize,
                             (int)smem_bytes);
        attr_set = true;
    }

    conv1_kernel<<<(BB*C1*16*16 + 255)/256, 256>>>(x, conv1_w, conv1_b);
    vproj_kernel<<<MM, DD>>>(lookup, Wv);              // independent of conv path
    conv2_kernel<<<(2*BB*C2*64 + 255)/256, 256>>>(conv2_w, conv2_b);
    hopfield_kernel<<<dim3(16, BB), 256, smem_bytes>>>(lookup, Wo, out);
}